// round 1
// baseline (speedup 1.0000x reference)
#include <cuda_runtime.h>

// ---------------------------------------------------------------------------
// CustomCNN (LeNet-like), batch 8192.
// Key identity: the bugged AvgPool means over channels AND window, then
// replicates across channels => all channels identical after each pool.
// Hence conv2 collapses to a channel-summed kernel over a single-channel
// input, and conv3 collapses to a 25->120 dot product.
//
// Pipeline per image (one CTA, everything in SMEM):
//   conv1(3->6, 5x5) + tanh + channel-mean  -> m1[28,28]
//   2x2 avg                                  -> p1[14,14]
//   conv2sum(1->16, 5x5) + tanh + mean/16    -> m2[10,10] (4 partials)
//   2x2 avg                                  -> p2[25]
//   k3sum dot (25->120) + tanh               -> h3[120]
//   fc1 (120->84) + tanh                     -> f[84]
//   fc2 (84->10)                             -> out
// ---------------------------------------------------------------------------

#define MAIN_THREADS 224

__device__ float g_k2s[16 * 25];    // channel-summed conv2 kernels
__device__ float g_k3sT[25 * 120];  // channel-summed conv3, transposed [i][o]

__global__ void prep_kernel(const float* __restrict__ k2,
                            const float* __restrict__ k3) {
    int t = threadIdx.x;
    if (t < 400) {
        int o = t / 25, i = t % 25;
        float s = 0.f;
#pragma unroll
        for (int c = 0; c < 6; c++) s += k2[(o * 6 + c) * 25 + i];
        g_k2s[t] = s;
    }
    for (int idx = t; idx < 3000; idx += blockDim.x) {
        int i = idx / 120, o = idx % 120;   // store transposed: [i][o]
        float s = 0.f;
#pragma unroll
        for (int c = 0; c < 16; c++) s += k3[(o * 16 + c) * 25 + i];
        g_k3sT[idx] = s;
    }
}

__global__ __launch_bounds__(MAIN_THREADS)
void lenet_fused_kernel(const float* __restrict__ x,
                        const float* __restrict__ k1,
                        const float* __restrict__ W1,
                        const float* __restrict__ b1,
                        const float* __restrict__ W2,
                        const float* __restrict__ b2,
                        float* __restrict__ out) {
    // Image padded to 33-float rows to avoid 32-bank conflicts.
    __shared__ float s_img[3 * 32 * 33];   // 3168
    __shared__ float s_k1[6 * 3 * 25];     // 450
    __shared__ float s_k2s[16 * 25];       // 400
    __shared__ float s_m1[28 * 28];        // 784
    __shared__ float s_p1[14 * 14];        // 196
    __shared__ float s_m2p[4 * 100];       // conv2 partial tanh-sums
    __shared__ float s_p2[25];
    __shared__ float s_h3[120];
    __shared__ float s_f[84];

    const int tid = threadIdx.x;
    const int img = blockIdx.x;
    const float* xi = x + (size_t)img * 3072;

    // ---- stage 0: load image (row-padded) + weights into SMEM ----
    for (int i = tid; i < 3072; i += MAIN_THREADS) {
        int c = i >> 10;            // /1024
        int rem = i & 1023;
        int y = rem >> 5;           // /32
        int xc = rem & 31;
        s_img[c * (32 * 33) + y * 33 + xc] = xi[i];
    }
    for (int i = tid; i < 450; i += MAIN_THREADS) s_k1[i] = k1[i];
    for (int i = tid; i < 400; i += MAIN_THREADS) s_k2s[i] = g_k2s[i];
    __syncthreads();

    // ---- stage 1: conv1 (3->6) + tanh + channel mean -> s_m1[28][28] ----
    // 196 tasks: each computes 4 adjacent output columns of one row.
    if (tid < 196) {
        int row = tid / 7;       // 0..27
        int seg = tid % 7;       // 0..6 -> cols seg*4 .. seg*4+3
        int x0 = seg * 4;

        float acc[6][4];
#pragma unroll
        for (int o = 0; o < 6; o++)
#pragma unroll
            for (int j = 0; j < 4; j++) acc[o][j] = 0.f;

        for (int c = 0; c < 3; c++) {
#pragma unroll
            for (int ky = 0; ky < 5; ky++) {
                const float* rp = s_img + c * (32 * 33) + (row + ky) * 33 + x0;
                float r[8];
#pragma unroll
                for (int j = 0; j < 8; j++) r[j] = rp[j];
#pragma unroll
                for (int o = 0; o < 6; o++) {
                    const float* wp = s_k1 + (o * 3 + c) * 25 + ky * 5;
#pragma unroll
                    for (int kx = 0; kx < 5; kx++) {
                        float w = wp[kx];
#pragma unroll
                        for (int j = 0; j < 4; j++) acc[o][j] += r[kx + j] * w;
                    }
                }
            }
        }
        float m[4] = {0.f, 0.f, 0.f, 0.f};
#pragma unroll
        for (int o = 0; o < 6; o++)
#pragma unroll
            for (int j = 0; j < 4; j++) m[j] += tanhf(acc[o][j]);
#pragma unroll
        for (int j = 0; j < 4; j++)
            s_m1[row * 28 + x0 + j] = m[j] * (1.0f / 6.0f);
    }
    __syncthreads();

    // ---- stage 2: 2x2 avg pool -> s_p1[14][14] ----
    if (tid < 196) {
        int y = tid / 14, xx = tid % 14;
        const float* a = s_m1 + (2 * y) * 28 + 2 * xx;
        s_p1[tid] = 0.25f * (a[0] + a[1] + a[28] + a[29]);
    }
    __syncthreads();

    // ---- stage 3: conv2sum (1->16) + tanh, 4-channel partials ----
    for (int t = tid; t < 400; t += MAIN_THREADS) {
        int og = t / 100;        // output-channel group (4 each)
        int pix = t % 100;
        int y = pix / 10, xx = pix % 10;
        float partial = 0.f;
#pragma unroll
        for (int oo = 0; oo < 4; oo++) {
            int o = og * 4 + oo;
            const float* wp = s_k2s + o * 25;
            float a = 0.f;
#pragma unroll
            for (int ky = 0; ky < 5; ky++)
#pragma unroll
                for (int kx = 0; kx < 5; kx++)
                    a += s_p1[(y + ky) * 14 + xx + kx] * wp[ky * 5 + kx];
            partial += tanhf(a);
        }
        s_m2p[t] = partial;
    }
    __syncthreads();

    // ---- stage 4: mean/16 + 2x2 pool -> s_p2[25] ----
    if (tid < 25) {
        int y = tid / 5, xx = tid % 5;
        float s = 0.f;
#pragma unroll
        for (int og = 0; og < 4; og++) {
            const float* mp = s_m2p + og * 100;
            s += mp[(2 * y) * 10 + 2 * xx] + mp[(2 * y) * 10 + 2 * xx + 1] +
                 mp[(2 * y + 1) * 10 + 2 * xx] + mp[(2 * y + 1) * 10 + 2 * xx + 1];
        }
        s_p2[tid] = s * (0.25f / 16.0f);
    }
    __syncthreads();

    // ---- stage 5: k3sum dot (25->120) + tanh -> s_h3 ----
    if (tid < 120) {
        float a = 0.f;
#pragma unroll
        for (int i = 0; i < 25; i++) a += s_p2[i] * g_k3sT[i * 120 + tid];
        s_h3[tid] = tanhf(a);
    }
    __syncthreads();

    // ---- stage 6: fc1 (120->84) + tanh ----
    if (tid < 84) {
        float a = b1[tid];
#pragma unroll 8
        for (int i = 0; i < 120; i++) a += s_h3[i] * W1[i * 84 + tid];
        s_f[tid] = tanhf(a);
    }
    __syncthreads();

    // ---- stage 7: fc2 (84->10) ----
    if (tid < 10) {
        float a = b2[tid];
#pragma unroll
        for (int j = 0; j < 84; j++) a += s_f[j] * W2[j * 10 + tid];
        out[(size_t)img * 10 + tid] = a;
    }
}

extern "C" void kernel_launch(void* const* d_in, const int* in_sizes, int n_in,
                              void* d_out, int out_size) {
    const float* x  = (const float*)d_in[0];   // [8192,3,32,32]
    const float* k1 = (const float*)d_in[1];   // [6,3,5,5]
    const float* k2 = (const float*)d_in[2];   // [16,6,5,5]
    const float* k3 = (const float*)d_in[3];   // [120,16,5,5]
    const float* W1 = (const float*)d_in[4];   // [120,84]
    const float* b1 = (const float*)d_in[5];   // [84]
    const float* W2 = (const float*)d_in[6];   // [84,10]
    const float* b2 = (const float*)d_in[7];   // [10]
    float* out = (float*)d_out;                // [8192,10]

    int batch = in_sizes[0] / 3072;

    prep_kernel<<<1, 512>>>(k2, k3);
    lenet_fused_kernel<<<batch, MAIN_THREADS>>>(x, k1, W1, b1, W2, b2, out);
}

// round 6
// speedup vs baseline: 1.0736x; 1.0736x over previous
#include <cuda_runtime.h>

// ---------------------------------------------------------------------------
// CustomCNN (LeNet-like), batch 8192, sm_100a.
// Channel-collapse identity (bugged AvgPool => identical channels after pool)
// reduces the net to: conv1(3->6)+tanh+mean+pool -> conv2sum(1->16)+tanh+mean
// +pool -> 25->120 dot -> fc1 -> fc2.
// f32x2 packed FMA (output-channel pairs), fast tanh via EX2+RCP, vectorized
// SMEM weight/image loads, 2 images per CTA.
// R5 fix: weight repack used `if (tid < 450)` with 224 threads -> half of
// conv1 weights never written. Now a strided loop. (Stage 5 already strided.)
// ---------------------------------------------------------------------------

#define MAIN_THREADS 224
typedef unsigned long long u64;

__device__ float g_k2t[25 * 16];    // conv2 channel-summed, transposed [i][o]
__device__ float g_k3sT[25 * 120];  // conv3 channel-summed, transposed [i][o]

__device__ __forceinline__ u64 pack2(float lo, float hi) {
    u64 r; asm("mov.b64 %0, {%1,%2};" : "=l"(r) : "f"(lo), "f"(hi)); return r;
}
__device__ __forceinline__ void unpack2(u64 v, float& lo, float& hi) {
    asm("mov.b64 {%0,%1}, %2;" : "=f"(lo), "=f"(hi) : "l"(v));
}
__device__ __forceinline__ u64 ffma2(u64 a, u64 b, u64 c) {
    u64 d; asm("fma.rn.f32x2 %0, %1, %2, %3;" : "=l"(d) : "l"(a), "l"(b), "l"(c));
    return d;
}
__device__ __forceinline__ float ftanh(float x) {
    x = fminf(fmaxf(x, -15.0f), 15.0f);
    float e = __expf(2.0f * x);
    return __fdividef(e - 1.0f, e + 1.0f);
}

__global__ void prep_kernel(const float* __restrict__ k2,
                            const float* __restrict__ k3) {
    int t = threadIdx.x;
    if (t < 400) {
        int i = t / 16, o = t % 16;   // transposed [i][o]
        float s = 0.f;
#pragma unroll
        for (int c = 0; c < 6; c++) s += k2[(o * 6 + c) * 25 + i];
        g_k2t[t] = s;
    }
    for (int idx = t; idx < 3000; idx += blockDim.x) {
        int i = idx / 120, o = idx % 120;   // transposed [i][o]
        float s = 0.f;
#pragma unroll
        for (int c = 0; c < 16; c++) s += k3[(o * 16 + c) * 25 + i];
        g_k3sT[idx] = s;
    }
}

__global__ __launch_bounds__(MAIN_THREADS, 4)
void lenet_fused_kernel(const float* __restrict__ x,
                        const float* __restrict__ k1,
                        const float* __restrict__ W1,
                        const float* __restrict__ b1,
                        const float* __restrict__ W2,
                        const float* __restrict__ b2,
                        float* __restrict__ out,
                        int batch) {
    // 2 images per CTA. Image rows padded to 36 floats (16B-aligned rows).
    __shared__ __align__(16) float s_img[2 * 3 * 32 * 36];  // 6912
    __shared__ __align__(16) float s_w1[3 * 5 * 5 * 6];     // [c][ky][kx][o] 450
    __shared__ __align__(16) float s_k2t[25 * 16];          // [i][o] 400
    __shared__ float s_m1[2 * 28 * 28];                     // 1568
    __shared__ float s_p1[2 * 14 * 14];                     // 392
    __shared__ float s_m2[2 * 100];                         // conv2 tanh-sums
    __shared__ float s_p2[2 * 25];
    __shared__ float s_h3[2 * 120];
    __shared__ float s_f[2 * 84];

    const int tid = threadIdx.x;
    const int base = blockIdx.x * 2;
    const int nimg = (base + 2 <= batch) ? 2 : (batch - base);

    // ---- stage 0: load images (row-padded) + repack weights into SMEM ----
    for (int v = 0; v < nimg; v++) {
        const float* xi = x + (size_t)(base + v) * 3072;
        float* si = s_img + v * 3456;
        for (int i = tid; i < 3072; i += MAIN_THREADS) {
            int c = i >> 10;
            int y = (i >> 5) & 31;
            int xc = i & 31;
            si[c * (32 * 36) + y * 36 + xc] = xi[i];
        }
    }
    // k1 layout [o][c][ky][kx] -> s_w1[((c*5+ky)*5+kx)*6 + o]
    // 450 entries on 224 threads: MUST be strided (R5 fix; was `if tid<450`).
    for (int i = tid; i < 450; i += MAIN_THREADS) {
        int o = i / 75, rem = i % 75;
        int c = rem / 25, ky = (rem % 25) / 5, kx = rem % 5;
        s_w1[((c * 5 + ky) * 5 + kx) * 6 + o] = k1[i];
    }
    for (int i = tid; i < 400; i += MAIN_THREADS) s_k2t[i] = g_k2t[i];
    __syncthreads();

    // ---- stage 1: conv1 (3->6) + tanh + channel mean -> s_m1 ----
    // Per image, 196 tasks: one row x 4 adjacent cols; channel pairs via f32x2.
    for (int v = 0; v < nimg; v++) {
        if (tid < 196) {
            int row = tid / 7;
            int x0 = (tid % 7) * 4;
            const float* img = s_img + v * 3456;

            u64 acc[3][4];
#pragma unroll
            for (int p = 0; p < 3; p++)
#pragma unroll
                for (int j = 0; j < 4; j++) acc[p][j] = 0ull;

#pragma unroll
            for (int c = 0; c < 3; c++) {
#pragma unroll
                for (int ky = 0; ky < 5; ky++) {
                    const float* rp = img + c * (32 * 36) + (row + ky) * 36 + x0;
                    float4 ra = *reinterpret_cast<const float4*>(rp);
                    float4 rb = *reinterpret_cast<const float4*>(rp + 4);
                    float r[8] = {ra.x, ra.y, ra.z, ra.w, rb.x, rb.y, rb.z, rb.w};
                    u64 rB[8];
#pragma unroll
                    for (int k = 0; k < 8; k++) rB[k] = pack2(r[k], r[k]);

                    const float* wb = s_w1 + ((c * 5 + ky) * 5) * 6;
#pragma unroll
                    for (int kx = 0; kx < 5; kx++) {
#pragma unroll
                        for (int p = 0; p < 3; p++) {
                            u64 w = *reinterpret_cast<const u64*>(wb + kx * 6 + 2 * p);
#pragma unroll
                            for (int j = 0; j < 4; j++)
                                acc[p][j] = ffma2(rB[kx + j], w, acc[p][j]);
                        }
                    }
                }
            }
            float m[4] = {0.f, 0.f, 0.f, 0.f};
#pragma unroll
            for (int p = 0; p < 3; p++)
#pragma unroll
                for (int j = 0; j < 4; j++) {
                    float a0, a1;
                    unpack2(acc[p][j], a0, a1);
                    m[j] += ftanh(a0) + ftanh(a1);
                }
#pragma unroll
            for (int j = 0; j < 4; j++)
                s_m1[v * 784 + row * 28 + x0 + j] = m[j] * (1.0f / 6.0f);
        }
    }
    __syncthreads();

    // ---- stage 2: 2x2 avg pool -> s_p1 ----
    if (tid < 196) {
        int y = tid / 14, xx = tid % 14;
        for (int v = 0; v < nimg; v++) {
            const float* a = s_m1 + v * 784 + (2 * y) * 28 + 2 * xx;
            s_p1[v * 196 + tid] = 0.25f * (a[0] + a[1] + a[28] + a[29]);
        }
    }
    __syncthreads();

    // ---- stage 3: conv2sum (1->16) + tanh, channel-paired f32x2 ----
    if (tid < 200) {
        int v = tid / 100;
        if (v < nimg) {
            int pix = tid % 100;
            int y = pix / 10, xx = pix % 10;
            const float* p1 = s_p1 + v * 196;
            u64 acc[8];
#pragma unroll
            for (int p = 0; p < 8; p++) acc[p] = 0ull;
#pragma unroll
            for (int ky = 0; ky < 5; ky++)
#pragma unroll
                for (int kx = 0; kx < 5; kx++) {
                    int i = ky * 5 + kx;
                    float wv = p1[(y + ky) * 14 + xx + kx];
                    u64 wB = pack2(wv, wv);
                    const float* kp = s_k2t + i * 16;
#pragma unroll
                    for (int p = 0; p < 8; p++)
                        acc[p] = ffma2(wB,
                                       *reinterpret_cast<const u64*>(kp + 2 * p),
                                       acc[p]);
                }
            float s = 0.f;
#pragma unroll
            for (int p = 0; p < 8; p++) {
                float a0, a1;
                unpack2(acc[p], a0, a1);
                s += ftanh(a0) + ftanh(a1);
            }
            s_m2[v * 100 + pix] = s;   // raw sum of 16 tanh
        }
    }
    __syncthreads();

    // ---- stage 4: channel-mean(/16) + 2x2 pool -> s_p2[25] ----
    if (tid < 50) {
        int v = tid / 25;
        if (v < nimg) {
            int t = tid % 25;
            int y = t / 5, xx = t % 5;
            const float* mp = s_m2 + v * 100;
            float s = mp[(2 * y) * 10 + 2 * xx] + mp[(2 * y) * 10 + 2 * xx + 1] +
                      mp[(2 * y + 1) * 10 + 2 * xx] + mp[(2 * y + 1) * 10 + 2 * xx + 1];
            s_p2[v * 25 + t] = s * (0.25f / 16.0f);
        }
    }
    __syncthreads();

    // ---- stage 5: k3sum dot (25->120) + tanh -> s_h3 ----
    // 240 tasks on 224 threads: strided loop.
    for (int t = tid; t < 240; t += MAIN_THREADS) {
        int v = t / 120;
        if (v < nimg) {
            int o = t % 120;
            const float* p2 = s_p2 + v * 25;
            float a = 0.f;
#pragma unroll
            for (int i = 0; i < 25; i++) a += p2[i] * g_k3sT[i * 120 + o];
            s_h3[v * 120 + o] = ftanh(a);
        }
    }
    __syncthreads();

    // ---- stage 6: fc1 (120->84) + tanh ----
    if (tid < 168) {
        int v = tid / 84;
        if (v < nimg) {
            int o = tid % 84;
            const float* h3 = s_h3 + v * 120;
            float a = b1[o];
#pragma unroll 8
            for (int i = 0; i < 120; i++) a += h3[i] * W1[i * 84 + o];
            s_f[v * 84 + o] = ftanh(a);
        }
    }
    __syncthreads();

    // ---- stage 7: fc2 (84->10) ----
    if (tid < 20) {
        int v = tid / 10;
        if (v < nimg) {
            int o = tid % 10;
            const float* f = s_f + v * 84;
            float a = b2[o];
#pragma unroll
            for (int j = 0; j < 84; j++) a += f[j] * W2[j * 10 + o];
            out[(size_t)(base + v) * 10 + o] = a;
        }
    }
}

extern "C" void kernel_launch(void* const* d_in, const int* in_sizes, int n_in,
                              void* d_out, int out_size) {
    const float* x  = (const float*)d_in[0];   // [B,3,32,32]
    const float* k1 = (const float*)d_in[1];   // [6,3,5,5]
    const float* k2 = (const float*)d_in[2];   // [16,6,5,5]
    const float* k3 = (const float*)d_in[3];   // [120,16,5,5]
    const float* W1 = (const float*)d_in[4];   // [120,84]
    const float* b1 = (const float*)d_in[5];   // [84]
    const float* W2 = (const float*)d_in[6];   // [84,10]
    const float* b2 = (const float*)d_in[7];   // [10]
    float* out = (float*)d_out;                // [B,10]

    int batch = in_sizes[0] / 3072;
    int blocks = (batch + 1) / 2;

    prep_kernel<<<1, 512>>>(k2, k3);
    lenet_fused_kernel<<<blocks, MAIN_THREADS>>>(x, k1, W1, b1, W2, b2, out, batch);
}

// round 8
// speedup vs baseline: 1.3255x; 1.2346x over previous
#include <cuda_runtime.h>

// ---------------------------------------------------------------------------
// CustomCNN (LeNet-like), batch 8192, sm_100a.
// Channel-collapse identity => conv1(3->6)+tanh+mean+pool -> conv2sum(1->16)
// +tanh+mean+pool -> 25->120 dot -> fc1 -> fc2.
// R7/R8: L1/LDS-pressure reduction. conv1: 2-row register blocking, images
// parallel across threads, weights via LDS.128+LDS.64 (8-padded layout).
// conv2: 2 pixels/thread, weights via LDS.128. f32x2 FMA throughout.
// (Resubmission after infra failure; guards/bounds/alignment audited.)
// ---------------------------------------------------------------------------

#define MAIN_THREADS 224
typedef unsigned long long u64;

__device__ float g_k2t[25 * 16];    // conv2 channel-summed, transposed [i][o]
__device__ float g_k3sT[25 * 120];  // conv3 channel-summed, transposed [i][o]

__device__ __forceinline__ u64 pack2(float lo, float hi) {
    u64 r; asm("mov.b64 %0, {%1,%2};" : "=l"(r) : "f"(lo), "f"(hi)); return r;
}
__device__ __forceinline__ void unpack2(u64 v, float& lo, float& hi) {
    asm("mov.b64 {%0,%1}, %2;" : "=f"(lo), "=f"(hi) : "l"(v));
}
__device__ __forceinline__ u64 ffma2(u64 a, u64 b, u64 c) {
    u64 d; asm("fma.rn.f32x2 %0, %1, %2, %3;" : "=l"(d) : "l"(a), "l"(b), "l"(c));
    return d;
}
__device__ __forceinline__ float ftanh(float x) {
    x = fminf(fmaxf(x, -15.0f), 15.0f);
    float e = __expf(2.0f * x);
    return __fdividef(e - 1.0f, e + 1.0f);
}

__global__ void prep_kernel(const float* __restrict__ k2,
                            const float* __restrict__ k3) {
    int t = threadIdx.x;
    if (t < 400) {
        int i = t / 16, o = t % 16;   // transposed [i][o]
        float s = 0.f;
#pragma unroll
        for (int c = 0; c < 6; c++) s += k2[(o * 6 + c) * 25 + i];
        g_k2t[t] = s;
    }
    for (int idx = t; idx < 3000; idx += blockDim.x) {
        int i = idx / 120, o = idx % 120;   // transposed [i][o]
        float s = 0.f;
#pragma unroll
        for (int c = 0; c < 16; c++) s += k3[(o * 16 + c) * 25 + i];
        g_k3sT[idx] = s;
    }
}

__global__ __launch_bounds__(MAIN_THREADS, 3)
void lenet_fused_kernel(const float* __restrict__ x,
                        const float* __restrict__ k1,
                        const float* __restrict__ W1,
                        const float* __restrict__ b1,
                        const float* __restrict__ W2,
                        const float* __restrict__ b2,
                        float* __restrict__ out,
                        int batch) {
    // 2 images per CTA. Image rows padded to 36 floats (16B-aligned rows).
    __shared__ __align__(16) float s_img[2 * 3 * 32 * 36];  // 6912
    __shared__ __align__(16) float s_w1[3 * 5 * 5 * 8];     // [c][ky][kx][8] 600
    __shared__ __align__(16) float s_k2t[25 * 16];          // [i][o] 400
    __shared__ float s_m1[2 * 28 * 28];                     // 1568
    __shared__ float s_p1[2 * 14 * 14];                     // 392
    __shared__ float s_m2[2 * 100];                         // conv2 tanh-sums
    __shared__ float s_p2[2 * 25];
    __shared__ float s_h3[2 * 120];
    __shared__ float s_f[2 * 84];

    const int tid = threadIdx.x;
    const int base = blockIdx.x * 2;
    const int nimg = (base + 2 <= batch) ? 2 : (batch - base);

    // ---- stage 0: load images (row-padded) + repack weights into SMEM ----
    for (int v = 0; v < nimg; v++) {
        const float* xi = x + (size_t)(base + v) * 3072;
        float* si = s_img + v * 3456;
        for (int i = tid; i < 3072; i += MAIN_THREADS) {
            int c = i >> 10;
            int y = (i >> 5) & 31;
            int xc = i & 31;
            si[c * (32 * 36) + y * 36 + xc] = xi[i];
        }
    }
    // k1 [o][c][ky][kx] -> s_w1[((c*5+ky)*5+kx)*8 + o], o>=6 zero-padded.
    // 600 entries on 224 threads: strided.
    for (int i = tid; i < 600; i += MAIN_THREADS) {
        int ch = i & 7;
        int rest = i >> 3;                 // (c*5+ky)*5+kx, 0..74
        int c = rest / 25, ky = (rest % 25) / 5, kx = rest % 5;
        s_w1[i] = (ch < 6) ? k1[((ch * 3 + c) * 5 + ky) * 5 + kx] : 0.f;
    }
    for (int i = tid; i < 400; i += MAIN_THREADS) s_k2t[i] = g_k2t[i];
    __syncthreads();

    // ---- stage 1: conv1 (3->6) + tanh + channel mean -> s_m1 ----
    // 98 threads per image (both images in parallel). Each thread: 2 rows x
    // 4 cols, rolling row-register window, channel-paired f32x2.
    if (tid < 196) {
        int v = tid / 98;
        if (v < nimg) {
            int t = tid % 98;
            int r2 = t / 7;              // row pair 0..13
            int x0 = (t % 7) * 4;
            const float* img = s_img + v * 3456;

            u64 acc[2][3][4];
#pragma unroll
            for (int r = 0; r < 2; r++)
#pragma unroll
                for (int p = 0; p < 3; p++)
#pragma unroll
                    for (int j = 0; j < 4; j++) acc[r][p][j] = 0ull;

#pragma unroll 1
            for (int c = 0; c < 3; c++) {
                const float* cb = img + c * 1152;
                u64 rcur[8];
                {
                    const float* rp = cb + (2 * r2) * 36 + x0;
                    float4 a = *reinterpret_cast<const float4*>(rp);
                    float4 b = *reinterpret_cast<const float4*>(rp + 4);
                    rcur[0] = pack2(a.x, a.x); rcur[1] = pack2(a.y, a.y);
                    rcur[2] = pack2(a.z, a.z); rcur[3] = pack2(a.w, a.w);
                    rcur[4] = pack2(b.x, b.x); rcur[5] = pack2(b.y, b.y);
                    rcur[6] = pack2(b.z, b.z); rcur[7] = pack2(b.w, b.w);
                }
#pragma unroll
                for (int ky = 0; ky < 5; ky++) {
                    u64 rnx[8];
                    {
                        const float* rp = cb + (2 * r2 + ky + 1) * 36 + x0;
                        float4 a = *reinterpret_cast<const float4*>(rp);
                        float4 b = *reinterpret_cast<const float4*>(rp + 4);
                        rnx[0] = pack2(a.x, a.x); rnx[1] = pack2(a.y, a.y);
                        rnx[2] = pack2(a.z, a.z); rnx[3] = pack2(a.w, a.w);
                        rnx[4] = pack2(b.x, b.x); rnx[5] = pack2(b.y, b.y);
                        rnx[6] = pack2(b.z, b.z); rnx[7] = pack2(b.w, b.w);
                    }
                    const float* wb = s_w1 + ((c * 5 + ky) * 5) * 8;
#pragma unroll
                    for (int kx = 0; kx < 5; kx++) {
                        ulonglong2 wA =
                            *reinterpret_cast<const ulonglong2*>(wb + kx * 8);
                        u64 wC = *reinterpret_cast<const u64*>(wb + kx * 8 + 4);
#pragma unroll
                        for (int j = 0; j < 4; j++) {
                            acc[0][0][j] = ffma2(rcur[kx + j], wA.x, acc[0][0][j]);
                            acc[0][1][j] = ffma2(rcur[kx + j], wA.y, acc[0][1][j]);
                            acc[0][2][j] = ffma2(rcur[kx + j], wC,   acc[0][2][j]);
                            acc[1][0][j] = ffma2(rnx[kx + j],  wA.x, acc[1][0][j]);
                            acc[1][1][j] = ffma2(rnx[kx + j],  wA.y, acc[1][1][j]);
                            acc[1][2][j] = ffma2(rnx[kx + j],  wC,   acc[1][2][j]);
                        }
                    }
#pragma unroll
                    for (int k = 0; k < 8; k++) rcur[k] = rnx[k];
                }
            }
#pragma unroll
            for (int r = 0; r < 2; r++) {
                float m[4] = {0.f, 0.f, 0.f, 0.f};
#pragma unroll
                for (int p = 0; p < 3; p++)
#pragma unroll
                    for (int j = 0; j < 4; j++) {
                        float a0, a1;
                        unpack2(acc[r][p][j], a0, a1);
                        m[j] += ftanh(a0) + ftanh(a1);
                    }
                int row = 2 * r2 + r;
#pragma unroll
                for (int j = 0; j < 4; j++)
                    s_m1[v * 784 + row * 28 + x0 + j] = m[j] * (1.0f / 6.0f);
            }
        }
    }
    __syncthreads();

    // ---- stage 2: 2x2 avg pool -> s_p1 ----
    if (tid < 196) {
        int y = tid / 14, xx = tid % 14;
        for (int v = 0; v < nimg; v++) {
            const float* a = s_m1 + v * 784 + (2 * y) * 28 + 2 * xx;
            s_p1[v * 196 + tid] = 0.25f * (a[0] + a[1] + a[28] + a[29]);
        }
    }
    __syncthreads();

    // ---- stage 3: conv2sum (1->16) + tanh, 2 pixels/thread, LDS.128 weights
    if (tid < 100) {
        int v = tid / 50;
        if (v < nimg) {
            int q = tid % 50;
            int y = q / 5, xp = (q % 5) * 2;   // pixels (y,xp),(y,xp+1)
            const float* p1 = s_p1 + v * 196;
            u64 acc0[8], acc1[8];
#pragma unroll
            for (int p = 0; p < 8; p++) { acc0[p] = 0ull; acc1[p] = 0ull; }
#pragma unroll
            for (int ky = 0; ky < 5; ky++) {
                const float* rp = p1 + (y + ky) * 14 + xp;
                u64 rb[6];
#pragma unroll
                for (int k = 0; k < 6; k++) {
                    float val = rp[k];
                    rb[k] = pack2(val, val);
                }
                const float* kpB = s_k2t + (ky * 5) * 16;
#pragma unroll
                for (int kx = 0; kx < 5; kx++) {
                    const float* kp = kpB + kx * 16;
                    ulonglong2 wa = *reinterpret_cast<const ulonglong2*>(kp);
                    ulonglong2 wb2 = *reinterpret_cast<const ulonglong2*>(kp + 4);
                    ulonglong2 wc = *reinterpret_cast<const ulonglong2*>(kp + 8);
                    ulonglong2 wd = *reinterpret_cast<const ulonglong2*>(kp + 12);
                    u64 w[8] = {wa.x, wa.y, wb2.x, wb2.y, wc.x, wc.y, wd.x, wd.y};
#pragma unroll
                    for (int p = 0; p < 8; p++) {
                        acc0[p] = ffma2(rb[kx],     w[p], acc0[p]);
                        acc1[p] = ffma2(rb[kx + 1], w[p], acc1[p]);
                    }
                }
            }
            float s0 = 0.f, s1 = 0.f;
#pragma unroll
            for (int p = 0; p < 8; p++) {
                float a0, a1;
                unpack2(acc0[p], a0, a1);
                s0 += ftanh(a0) + ftanh(a1);
                unpack2(acc1[p], a0, a1);
                s1 += ftanh(a0) + ftanh(a1);
            }
            s_m2[v * 100 + y * 10 + xp]     = s0;
            s_m2[v * 100 + y * 10 + xp + 1] = s1;
        }
    }
    __syncthreads();

    // ---- stage 4: channel-mean(/16) + 2x2 pool -> s_p2[25] ----
    if (tid < 50) {
        int v = tid / 25;
        if (v < nimg) {
            int t = tid % 25;
            int y = t / 5, xx = t % 5;
            const float* mp = s_m2 + v * 100;
            float s = mp[(2 * y) * 10 + 2 * xx] + mp[(2 * y) * 10 + 2 * xx + 1] +
                      mp[(2 * y + 1) * 10 + 2 * xx] + mp[(2 * y + 1) * 10 + 2 * xx + 1];
            s_p2[v * 25 + t] = s * (0.25f / 16.0f);
        }
    }
    __syncthreads();

    // ---- stage 5: k3sum dot (25->120) + tanh -> s_h3 ----
    // 240 tasks on 224 threads: strided loop.
    for (int t = tid; t < 240; t += MAIN_THREADS) {
        int v = t / 120;
        if (v < nimg) {
            int o = t % 120;
            const float* p2 = s_p2 + v * 25;
            float a = 0.f;
#pragma unroll
            for (int i = 0; i < 25; i++) a += p2[i] * g_k3sT[i * 120 + o];
            s_h3[v * 120 + o] = ftanh(a);
        }
    }
    __syncthreads();

    // ---- stage 6: fc1 (120->84) + tanh ----
    if (tid < 168) {
        int v = tid / 84;
        if (v < nimg) {
            int o = tid % 84;
            const float* h3 = s_h3 + v * 120;
            float a = b1[o];
#pragma unroll 8
            for (int i = 0; i < 120; i++) a += h3[i] * W1[i * 84 + o];
            s_f[v * 84 + o] = ftanh(a);
        }
    }
    __syncthreads();

    // ---- stage 7: fc2 (84->10) ----
    if (tid < 20) {
        int v = tid / 10;
        if (v < nimg) {
            int o = tid % 10;
            const float* f = s_f + v * 84;
            float a = b2[o];
#pragma unroll
            for (int j = 0; j < 84; j++) a += f[j] * W2[j * 10 + o];
            out[(size_t)(base + v) * 10 + o] = a;
        }
    }
}

extern "C" void kernel_launch(void* const* d_in, const int* in_sizes, int n_in,
                              void* d_out, int out_size) {
    const float* x  = (const float*)d_in[0];   // [B,3,32,32]
    const float* k1 = (const float*)d_in[1];   // [6,3,5,5]
    const float* k2 = (const float*)d_in[2];   // [16,6,5,5]
    const float* k3 = (const float*)d_in[3];   // [120,16,5,5]
    const float* W1 = (const float*)d_in[4];   // [120,84]
    const float* b1 = (const float*)d_in[5];   // [84]
    const float* W2 = (const float*)d_in[6];   // [84,10]
    const float* b2 = (const float*)d_in[7];   // [10]
    float* out = (float*)d_out;                // [B,10]

    int batch = in_sizes[0] / 3072;
    int blocks = (batch + 1) / 2;

    prep_kernel<<<1, 512>>>(k2, k3);
    lenet_fused_kernel<<<blocks, MAIN_THREADS>>>(x, k1, W1, b1, W2, b2, out, batch);
}

// round 9
// speedup vs baseline: 1.4306x; 1.0793x over previous
#include <cuda_runtime.h>

// ---------------------------------------------------------------------------
// CustomCNN (LeNet-like), batch 8192, sm_100a.
// Channel-collapse identity => conv1(3->6)+tanh+mean+pool -> conv2sum(1->16)
// +tanh+mean+pool -> 25->120 dot -> fc1 -> fc2.
// R9: occupancy push. conv1 re-blocked to 1-row x 4-col tasks with a single
// live row (acc 24 + window 16 regs) so 5 CTAs/SM fit (was 3). 392 tasks in
// 2 strided passes. conv2: 200 threads, 1 px/thread. f32x2 FMA throughout.
// ---------------------------------------------------------------------------

#define MAIN_THREADS 224
typedef unsigned long long u64;

__device__ float g_k2t[25 * 16];    // conv2 channel-summed, transposed [i][o]
__device__ float g_k3sT[25 * 120];  // conv3 channel-summed, transposed [i][o]

__device__ __forceinline__ u64 pack2(float lo, float hi) {
    u64 r; asm("mov.b64 %0, {%1,%2};" : "=l"(r) : "f"(lo), "f"(hi)); return r;
}
__device__ __forceinline__ void unpack2(u64 v, float& lo, float& hi) {
    asm("mov.b64 {%0,%1}, %2;" : "=f"(lo), "=f"(hi) : "l"(v));
}
__device__ __forceinline__ u64 ffma2(u64 a, u64 b, u64 c) {
    u64 d; asm("fma.rn.f32x2 %0, %1, %2, %3;" : "=l"(d) : "l"(a), "l"(b), "l"(c));
    return d;
}
__device__ __forceinline__ float ftanh(float x) {
    x = fminf(fmaxf(x, -15.0f), 15.0f);
    float e = __expf(2.0f * x);
    return __fdividef(e - 1.0f, e + 1.0f);
}

__global__ void prep_kernel(const float* __restrict__ k2,
                            const float* __restrict__ k3) {
    int t = threadIdx.x;
    if (t < 400) {
        int i = t / 16, o = t % 16;   // transposed [i][o]
        float s = 0.f;
#pragma unroll
        for (int c = 0; c < 6; c++) s += k2[(o * 6 + c) * 25 + i];
        g_k2t[t] = s;
    }
    for (int idx = t; idx < 3000; idx += blockDim.x) {
        int i = idx / 120, o = idx % 120;   // transposed [i][o]
        float s = 0.f;
#pragma unroll
        for (int c = 0; c < 16; c++) s += k3[(o * 16 + c) * 25 + i];
        g_k3sT[idx] = s;
    }
}

__global__ __launch_bounds__(MAIN_THREADS, 5)
void lenet_fused_kernel(const float* __restrict__ x,
                        const float* __restrict__ k1,
                        const float* __restrict__ W1,
                        const float* __restrict__ b1,
                        const float* __restrict__ W2,
                        const float* __restrict__ b2,
                        float* __restrict__ out,
                        int batch) {
    // 2 images per CTA. Image rows padded to 36 floats (16B-aligned rows).
    __shared__ __align__(16) float s_img[2 * 3 * 32 * 36];  // 6912
    __shared__ __align__(16) float s_w1[3 * 5 * 5 * 8];     // [c][ky][kx][8] 600
    __shared__ __align__(16) float s_k2t[25 * 16];          // [i][o] 400
    __shared__ float s_m1[2 * 28 * 28];                     // 1568
    __shared__ float s_p1[2 * 14 * 14];                     // 392
    __shared__ float s_m2[2 * 100];                         // conv2 tanh-sums
    __shared__ float s_p2[2 * 25];
    __shared__ float s_h3[2 * 120];
    __shared__ float s_f[2 * 84];

    const int tid = threadIdx.x;
    const int base = blockIdx.x * 2;
    const int nimg = (base + 2 <= batch) ? 2 : (batch - base);

    // ---- stage 0: load images (row-padded) + repack weights into SMEM ----
    for (int v = 0; v < nimg; v++) {
        const float* xi = x + (size_t)(base + v) * 3072;
        float* si = s_img + v * 3456;
        for (int i = tid; i < 3072; i += MAIN_THREADS) {
            int c = i >> 10;
            int y = (i >> 5) & 31;
            int xc = i & 31;
            si[c * (32 * 36) + y * 36 + xc] = xi[i];
        }
    }
    // k1 [o][c][ky][kx] -> s_w1[((c*5+ky)*5+kx)*8 + o], o>=6 zero-padded.
    for (int i = tid; i < 600; i += MAIN_THREADS) {
        int ch = i & 7;
        int rest = i >> 3;                 // (c*5+ky)*5+kx, 0..74
        int c = rest / 25, ky = (rest % 25) / 5, kx = rest % 5;
        s_w1[i] = (ch < 6) ? k1[((ch * 3 + c) * 5 + ky) * 5 + kx] : 0.f;
    }
    for (int i = tid; i < 400; i += MAIN_THREADS) s_k2t[i] = g_k2t[i];
    __syncthreads();

    // ---- stage 1: conv1 (3->6) + tanh + channel mean -> s_m1 ----
    // 392 tasks (2 images x 28 rows x 7 col-segs), 2 strided passes.
    // Each task: 1 row x 4 cols, single live row window, f32x2 channel pairs.
#pragma unroll 1
    for (int pass = 0; pass < 2; pass++) {
        int q = tid + pass * MAIN_THREADS;
        if (q < 392) {
            int v = q / 196;
            if (v < nimg) {
                int t = q % 196;
                int row = t / 7;             // 0..27
                int x0 = (t % 7) * 4;
                const float* img = s_img + v * 3456;

                u64 acc[3][4];
#pragma unroll
                for (int p = 0; p < 3; p++)
#pragma unroll
                    for (int j = 0; j < 4; j++) acc[p][j] = 0ull;

#pragma unroll 1
                for (int c = 0; c < 3; c++) {
                    const float* cb = img + c * 1152;
#pragma unroll
                    for (int ky = 0; ky < 5; ky++) {
                        const float* rp = cb + (row + ky) * 36 + x0;
                        float4 a = *reinterpret_cast<const float4*>(rp);
                        float4 b = *reinterpret_cast<const float4*>(rp + 4);
                        u64 r8[8];
                        r8[0] = pack2(a.x, a.x); r8[1] = pack2(a.y, a.y);
                        r8[2] = pack2(a.z, a.z); r8[3] = pack2(a.w, a.w);
                        r8[4] = pack2(b.x, b.x); r8[5] = pack2(b.y, b.y);
                        r8[6] = pack2(b.z, b.z); r8[7] = pack2(b.w, b.w);

                        const float* wb = s_w1 + ((c * 5 + ky) * 5) * 8;
#pragma unroll
                        for (int kx = 0; kx < 5; kx++) {
                            ulonglong2 wA =
                                *reinterpret_cast<const ulonglong2*>(wb + kx * 8);
                            u64 wC =
                                *reinterpret_cast<const u64*>(wb + kx * 8 + 4);
#pragma unroll
                            for (int j = 0; j < 4; j++) {
                                acc[0][j] = ffma2(r8[kx + j], wA.x, acc[0][j]);
                                acc[1][j] = ffma2(r8[kx + j], wA.y, acc[1][j]);
                                acc[2][j] = ffma2(r8[kx + j], wC,   acc[2][j]);
                            }
                        }
                    }
                }
                float m[4] = {0.f, 0.f, 0.f, 0.f};
#pragma unroll
                for (int p = 0; p < 3; p++)
#pragma unroll
                    for (int j = 0; j < 4; j++) {
                        float a0, a1;
                        unpack2(acc[p][j], a0, a1);
                        m[j] += ftanh(a0) + ftanh(a1);
                    }
#pragma unroll
                for (int j = 0; j < 4; j++)
                    s_m1[v * 784 + row * 28 + x0 + j] = m[j] * (1.0f / 6.0f);
            }
        }
    }
    __syncthreads();

    // ---- stage 2: 2x2 avg pool -> s_p1 ----
    if (tid < 196) {
        int y = tid / 14, xx = tid % 14;
        for (int v = 0; v < nimg; v++) {
            const float* a = s_m1 + v * 784 + (2 * y) * 28 + 2 * xx;
            s_p1[v * 196 + tid] = 0.25f * (a[0] + a[1] + a[28] + a[29]);
        }
    }
    __syncthreads();

    // ---- stage 3: conv2sum (1->16) + tanh, 1 px/thread, LDS.128 weights ----
    if (tid < 200) {
        int v = tid / 100;
        if (v < nimg) {
            int pix = tid % 100;
            int y = pix / 10, xx = pix % 10;
            const float* p1 = s_p1 + v * 196;
            u64 acc[8];
#pragma unroll
            for (int p = 0; p < 8; p++) acc[p] = 0ull;
#pragma unroll
            for (int ky = 0; ky < 5; ky++) {
                const float* rp = p1 + (y + ky) * 14 + xx;
                u64 rb[5];
#pragma unroll
                for (int k = 0; k < 5; k++) {
                    float val = rp[k];
                    rb[k] = pack2(val, val);
                }
                const float* kpB = s_k2t + (ky * 5) * 16;
#pragma unroll
                for (int kx = 0; kx < 5; kx++) {
                    const float* kp = kpB + kx * 16;
                    ulonglong2 wa = *reinterpret_cast<const ulonglong2*>(kp);
                    ulonglong2 wb2 = *reinterpret_cast<const ulonglong2*>(kp + 4);
                    ulonglong2 wc = *reinterpret_cast<const ulonglong2*>(kp + 8);
                    ulonglong2 wd = *reinterpret_cast<const ulonglong2*>(kp + 12);
                    acc[0] = ffma2(rb[kx], wa.x, acc[0]);
                    acc[1] = ffma2(rb[kx], wa.y, acc[1]);
                    acc[2] = ffma2(rb[kx], wb2.x, acc[2]);
                    acc[3] = ffma2(rb[kx], wb2.y, acc[3]);
                    acc[4] = ffma2(rb[kx], wc.x, acc[4]);
                    acc[5] = ffma2(rb[kx], wc.y, acc[5]);
                    acc[6] = ffma2(rb[kx], wd.x, acc[6]);
                    acc[7] = ffma2(rb[kx], wd.y, acc[7]);
                }
            }
            float s = 0.f;
#pragma unroll
            for (int p = 0; p < 8; p++) {
                float a0, a1;
                unpack2(acc[p], a0, a1);
                s += ftanh(a0) + ftanh(a1);
            }
            s_m2[v * 100 + pix] = s;   // raw sum of 16 tanh
        }
    }
    __syncthreads();

    // ---- stage 4: channel-mean(/16) + 2x2 pool -> s_p2[25] ----
    if (tid < 50) {
        int v = tid / 25;
        if (v < nimg) {
            int t = tid % 25;
            int y = t / 5, xx = t % 5;
            const float* mp = s_m2 + v * 100;
            float s = mp[(2 * y) * 10 + 2 * xx] + mp[(2 * y) * 10 + 2 * xx + 1] +
                      mp[(2 * y + 1) * 10 + 2 * xx] + mp[(2 * y + 1) * 10 + 2 * xx + 1];
            s_p2[v * 25 + t] = s * (0.25f / 16.0f);
        }
    }
    __syncthreads();

    // ---- stage 5: k3sum dot (25->120) + tanh -> s_h3 ----
    for (int t = tid; t < 240; t += MAIN_THREADS) {
        int v = t / 120;
        if (v < nimg) {
            int o = t % 120;
            const float* p2 = s_p2 + v * 25;
            float a = 0.f;
#pragma unroll
            for (int i = 0; i < 25; i++) a += p2[i] * g_k3sT[i * 120 + o];
            s_h3[v * 120 + o] = ftanh(a);
        }
    }
    __syncthreads();

    // ---- stage 6: fc1 (120->84) + tanh ----
    if (tid < 168) {
        int v = tid / 84;
        if (v < nimg) {
            int o = tid % 84;
            const float* h3 = s_h3 + v * 120;
            float a = b1[o];
#pragma unroll 8
            for (int i = 0; i < 120; i++) a += h3[i] * W1[i * 84 + o];
            s_f[v * 84 + o] = ftanh(a);
        }
    }
    __syncthreads();

    // ---- stage 7: fc2 (84->10) ----
    if (tid < 20) {
        int v = tid / 10;
        if (v < nimg) {
            int o = tid % 10;
            const float* f = s_f + v * 84;
            float a = b2[o];
#pragma unroll
            for (int j = 0; j < 84; j++) a += f[j] * W2[j * 10 + o];
            out[(size_t)(base + v) * 10 + o] = a;
        }
    }
}

extern "C" void kernel_launch(void* const* d_in, const int* in_sizes, int n_in,
                              void* d_out, int out_size) {
    const float* x  = (const float*)d_in[0];   // [B,3,32,32]
    const float* k1 = (const float*)d_in[1];   // [6,3,5,5]
    const float* k2 = (const float*)d_in[2];   // [16,6,5,5]
    const float* k3 = (const float*)d_in[3];   // [120,16,5,5]
    const float* W1 = (const float*)d_in[4];   // [120,84]
    const float* b1 = (const float*)d_in[5];   // [84]
    const float* W2 = (const float*)d_in[6];   // [84,10]
    const float* b2 = (const float*)d_in[7];   // [10]
    float* out = (float*)d_out;                // [B,10]

    int batch = in_sizes[0] / 3072;
    int blocks = (batch + 1) / 2;

    prep_kernel<<<1, 512>>>(k2, k3);
    lenet_fused_kernel<<<blocks, MAIN_THREADS>>>(x, k1, W1, b1, W2, b2, out, batch);
}

// round 10
// speedup vs baseline: 1.6578x; 1.1588x over previous
#include <cuda_runtime.h>

// ---------------------------------------------------------------------------
// CustomCNN (LeNet-like), batch 8192, sm_100a.
// Channel-collapse identity => conv1(3->6)+tanh+mean+pool -> conv2sum(1->16)
// +tanh+mean+pool -> 25->120 dot -> fc1 -> fc2.
// R10: conv weights moved to __constant__ (LDC/LDCU port, off L1). prep
// kernel stages repacked tables in __device__ buffers; kernel_launch copies
// them to constant symbols with cudaMemcpyToSymbolAsync (D2D, capturable).
// Otherwise keeps R9 structure: 1-row x 4-col conv1 tasks, f32x2 FMA,
// fast tanh, 2 images/CTA, 5 CTAs/SM.
// ---------------------------------------------------------------------------

#define MAIN_THREADS 224
typedef unsigned long long u64;

// Staging (written by prep_kernel), then copied into __constant__.
__device__ float g_w1s[600];        // conv1 repacked [(c,ky,kx)][8ch pad]
__device__ float g_k2s[400];        // conv2 channel-summed [tap][16ch]
__device__ float g_k3sT[25 * 120];  // conv3 channel-summed, transposed [i][o]

// Constant tables (separate cache port; zero L1 wavefronts).
// c_w1x: 75 taps x 2 ulonglong2 (8 floats: ch pairs 01,23,45,pad).
// c_k2x: 25 taps x 4 ulonglong2 (16 floats: ch pairs 01..15).
__constant__ __align__(16) ulonglong2 c_w1x[150];
__constant__ __align__(16) ulonglong2 c_k2x[100];

__device__ __forceinline__ u64 pack2(float lo, float hi) {
    u64 r; asm("mov.b64 %0, {%1,%2};" : "=l"(r) : "f"(lo), "f"(hi)); return r;
}
__device__ __forceinline__ void unpack2(u64 v, float& lo, float& hi) {
    asm("mov.b64 {%0,%1}, %2;" : "=f"(lo), "=f"(hi) : "l"(v));
}
__device__ __forceinline__ u64 ffma2(u64 a, u64 b, u64 c) {
    u64 d; asm("fma.rn.f32x2 %0, %1, %2, %3;" : "=l"(d) : "l"(a), "l"(b), "l"(c));
    return d;
}
__device__ __forceinline__ float ftanh(float x) {
    x = fminf(fmaxf(x, -15.0f), 15.0f);
    float e = __expf(2.0f * x);
    return __fdividef(e - 1.0f, e + 1.0f);
}

__global__ void prep_kernel(const float* __restrict__ k1,
                            const float* __restrict__ k2,
                            const float* __restrict__ k3) {
    int t = threadIdx.x;
    // conv1: k1 [o][c][ky][kx] -> g_w1s[((c*5+ky)*5+kx)*8 + o], o>=6 zero.
    if (t < 600) {
        int ch = t & 7;
        int rest = t >> 3;                 // (c*5+ky)*5+kx
        int c = rest / 25, ky = (rest % 25) / 5, kx = rest % 5;
        g_w1s[t] = (ch < 6) ? k1[((ch * 3 + c) * 5 + ky) * 5 + kx] : 0.f;
    }
    // conv2: channel-sum, transposed [tap][16ch].
    if (t < 400) {
        int i = t / 16, o = t % 16;
        float s = 0.f;
#pragma unroll
        for (int c = 0; c < 6; c++) s += k2[(o * 6 + c) * 25 + i];
        g_k2s[t] = s;
    }
    // conv3: channel-sum, transposed [i][o].
    for (int idx = t; idx < 3000; idx += blockDim.x) {
        int i = idx / 120, o = idx % 120;
        float s = 0.f;
#pragma unroll
        for (int c = 0; c < 16; c++) s += k3[(o * 16 + c) * 25 + i];
        g_k3sT[idx] = s;
    }
}

__global__ __launch_bounds__(MAIN_THREADS, 5)
void lenet_fused_kernel(const float* __restrict__ x,
                        const float* __restrict__ W1,
                        const float* __restrict__ b1,
                        const float* __restrict__ W2,
                        const float* __restrict__ b2,
                        float* __restrict__ out,
                        int batch) {
    // 2 images per CTA. Image rows padded to 36 floats (16B-aligned rows).
    __shared__ __align__(16) float s_img[2 * 3 * 32 * 36];  // 6912
    __shared__ float s_m1[2 * 28 * 28];                     // 1568
    __shared__ float s_p1[2 * 14 * 14];                     // 392
    __shared__ float s_m2[2 * 100];                         // conv2 tanh-sums
    __shared__ float s_p2[2 * 25];
    __shared__ float s_h3[2 * 120];
    __shared__ float s_f[2 * 84];

    const int tid = threadIdx.x;
    const int base = blockIdx.x * 2;
    const int nimg = (base + 2 <= batch) ? 2 : (batch - base);

    // ---- stage 0: load images (row-padded) into SMEM ----
    for (int v = 0; v < nimg; v++) {
        const float* xi = x + (size_t)(base + v) * 3072;
        float* si = s_img + v * 3456;
        for (int i = tid; i < 3072; i += MAIN_THREADS) {
            int c = i >> 10;
            int y = (i >> 5) & 31;
            int xc = i & 31;
            si[c * (32 * 36) + y * 36 + xc] = xi[i];
        }
    }
    __syncthreads();

    // ---- stage 1: conv1 (3->6) + tanh + channel mean -> s_m1 ----
    // 392 tasks (2 images x 28 rows x 7 col-segs), 2 strided passes.
    // Weights from __constant__ (LDC), images from SMEM.
#pragma unroll 1
    for (int pass = 0; pass < 2; pass++) {
        int q = tid + pass * MAIN_THREADS;
        if (q < 392) {
            int v = q / 196;
            if (v < nimg) {
                int t = q % 196;
                int row = t / 7;             // 0..27
                int x0 = (t % 7) * 4;
                const float* img = s_img + v * 3456;

                u64 acc[3][4];
#pragma unroll
                for (int p = 0; p < 3; p++)
#pragma unroll
                    for (int j = 0; j < 4; j++) acc[p][j] = 0ull;

#pragma unroll 1
                for (int c = 0; c < 3; c++) {
                    const float* cb = img + c * 1152;
#pragma unroll
                    for (int ky = 0; ky < 5; ky++) {
                        const float* rp = cb + (row + ky) * 36 + x0;
                        float4 a = *reinterpret_cast<const float4*>(rp);
                        float4 b = *reinterpret_cast<const float4*>(rp + 4);
                        u64 r8[8];
                        r8[0] = pack2(a.x, a.x); r8[1] = pack2(a.y, a.y);
                        r8[2] = pack2(a.z, a.z); r8[3] = pack2(a.w, a.w);
                        r8[4] = pack2(b.x, b.x); r8[5] = pack2(b.y, b.y);
                        r8[6] = pack2(b.z, b.z); r8[7] = pack2(b.w, b.w);

                        int tapB = (c * 5 + ky) * 5;
#pragma unroll
                        for (int kx = 0; kx < 5; kx++) {
                            ulonglong2 wAB = c_w1x[(tapB + kx) * 2];
                            u64 wC = c_w1x[(tapB + kx) * 2 + 1].x;
#pragma unroll
                            for (int j = 0; j < 4; j++) {
                                acc[0][j] = ffma2(r8[kx + j], wAB.x, acc[0][j]);
                                acc[1][j] = ffma2(r8[kx + j], wAB.y, acc[1][j]);
                                acc[2][j] = ffma2(r8[kx + j], wC,    acc[2][j]);
                            }
                        }
                    }
                }
                float m[4] = {0.f, 0.f, 0.f, 0.f};
#pragma unroll
                for (int p = 0; p < 3; p++)
#pragma unroll
                    for (int j = 0; j < 4; j++) {
                        float a0, a1;
                        unpack2(acc[p][j], a0, a1);
                        m[j] += ftanh(a0) + ftanh(a1);
                    }
#pragma unroll
                for (int j = 0; j < 4; j++)
                    s_m1[v * 784 + row * 28 + x0 + j] = m[j] * (1.0f / 6.0f);
            }
        }
    }
    __syncthreads();

    // ---- stage 2: 2x2 avg pool -> s_p1 ----
    if (tid < 196) {
        int y = tid / 14, xx = tid % 14;
        for (int v = 0; v < nimg; v++) {
            const float* a = s_m1 + v * 784 + (2 * y) * 28 + 2 * xx;
            s_p1[v * 196 + tid] = 0.25f * (a[0] + a[1] + a[28] + a[29]);
        }
    }
    __syncthreads();

    // ---- stage 3: conv2sum (1->16) + tanh, 1 px/thread, constant weights ---
    if (tid < 200) {
        int v = tid / 100;
        if (v < nimg) {
            int pix = tid % 100;
            int y = pix / 10, xx = pix % 10;
            const float* p1 = s_p1 + v * 196;
            u64 acc[8];
#pragma unroll
            for (int p = 0; p < 8; p++) acc[p] = 0ull;
#pragma unroll
            for (int ky = 0; ky < 5; ky++) {
                const float* rp = p1 + (y + ky) * 14 + xx;
                u64 rb[5];
#pragma unroll
                for (int k = 0; k < 5; k++) {
                    float val = rp[k];
                    rb[k] = pack2(val, val);
                }
#pragma unroll
                for (int kx = 0; kx < 5; kx++) {
                    int i = ky * 5 + kx;
                    ulonglong2 w0 = c_k2x[i * 4];
                    ulonglong2 w1 = c_k2x[i * 4 + 1];
                    ulonglong2 w2 = c_k2x[i * 4 + 2];
                    ulonglong2 w3 = c_k2x[i * 4 + 3];
                    acc[0] = ffma2(rb[kx], w0.x, acc[0]);
                    acc[1] = ffma2(rb[kx], w0.y, acc[1]);
                    acc[2] = ffma2(rb[kx], w1.x, acc[2]);
                    acc[3] = ffma2(rb[kx], w1.y, acc[3]);
                    acc[4] = ffma2(rb[kx], w2.x, acc[4]);
                    acc[5] = ffma2(rb[kx], w2.y, acc[5]);
                    acc[6] = ffma2(rb[kx], w3.x, acc[6]);
                    acc[7] = ffma2(rb[kx], w3.y, acc[7]);
                }
            }
            float s = 0.f;
#pragma unroll
            for (int p = 0; p < 8; p++) {
                float a0, a1;
                unpack2(acc[p], a0, a1);
                s += ftanh(a0) + ftanh(a1);
            }
            s_m2[v * 100 + pix] = s;   // raw sum of 16 tanh
        }
    }
    __syncthreads();

    // ---- stage 4: channel-mean(/16) + 2x2 pool -> s_p2[25] ----
    if (tid < 50) {
        int v = tid / 25;
        if (v < nimg) {
            int t = tid % 25;
            int y = t / 5, xx = t % 5;
            const float* mp = s_m2 + v * 100;
            float s = mp[(2 * y) * 10 + 2 * xx] + mp[(2 * y) * 10 + 2 * xx + 1] +
                      mp[(2 * y + 1) * 10 + 2 * xx] + mp[(2 * y + 1) * 10 + 2 * xx + 1];
            s_p2[v * 25 + t] = s * (0.25f / 16.0f);
        }
    }
    __syncthreads();

    // ---- stage 5: k3sum dot (25->120) + tanh -> s_h3 ----
    for (int t = tid; t < 240; t += MAIN_THREADS) {
        int v = t / 120;
        if (v < nimg) {
            int o = t % 120;
            const float* p2 = s_p2 + v * 25;
            float a = 0.f;
#pragma unroll
            for (int i = 0; i < 25; i++) a += p2[i] * g_k3sT[i * 120 + o];
            s_h3[v * 120 + o] = ftanh(a);
        }
    }
    __syncthreads();

    // ---- stage 6: fc1 (120->84) + tanh ----
    if (tid < 168) {
        int v = tid / 84;
        if (v < nimg) {
            int o = tid % 84;
            const float* h3 = s_h3 + v * 120;
            float a = b1[o];
#pragma unroll 8
            for (int i = 0; i < 120; i++) a += h3[i] * W1[i * 84 + o];
            s_f[v * 84 + o] = ftanh(a);
        }
    }
    __syncthreads();

    // ---- stage 7: fc2 (84->10) ----
    if (tid < 20) {
        int v = tid / 10;
        if (v < nimg) {
            int o = tid % 10;
            const float* f = s_f + v * 84;
            float a = b2[o];
#pragma unroll
            for (int j = 0; j < 84; j++) a += f[j] * W2[j * 10 + o];
            out[(size_t)(base + v) * 10 + o] = a;
        }
    }
}

extern "C" void kernel_launch(void* const* d_in, const int* in_sizes, int n_in,
                              void* d_out, int out_size) {
    const float* x  = (const float*)d_in[0];   // [B,3,32,32]
    const float* k1 = (const float*)d_in[1];   // [6,3,5,5]
    const float* k2 = (const float*)d_in[2];   // [16,6,5,5]
    const float* k3 = (const float*)d_in[3];   // [120,16,5,5]
    const float* W1 = (const float*)d_in[4];   // [120,84]
    const float* b1 = (const float*)d_in[5];   // [84]
    const float* W2 = (const float*)d_in[6];   // [84,10]
    const float* b2 = (const float*)d_in[7];   // [10]
    float* out = (float*)d_out;                // [B,10]

    int batch = in_sizes[0] / 3072;
    int blocks = (batch + 1) / 2;

    prep_kernel<<<1, 640>>>(k1, k2, k3);

    // Publish staged weight tables to __constant__ (D2D async memcpys —
    // graph-capturable memcpy-to-symbol nodes).
    void* p_w1s = nullptr;
    void* p_k2s = nullptr;
    cudaGetSymbolAddress(&p_w1s, g_w1s);
    cudaGetSymbolAddress(&p_k2s, g_k2s);
    cudaMemcpyToSymbolAsync(c_w1x, p_w1s, 600 * sizeof(float), 0,
                            cudaMemcpyDeviceToDevice, 0);
    cudaMemcpyToSymbolAsync(c_k2x, p_k2s, 400 * sizeof(float), 0,
                            cudaMemcpyDeviceToDevice, 0);

    lenet_fused_kernel<<<blocks, MAIN_THREADS>>>(x, W1, b1, W2, b2, out, batch);
}